// round 16
// baseline (speedup 1.0000x reference)
#include <cuda_runtime.h>

// Problem constants
#define Bq   8
#define Np   4096
#define Cc   256
#define Sq   512
#define NSk  64
#define NROWS_L (Bq*Sq*NSk)   /* 262144 */
#define NROWS_G (Bq*Np)       /* 32768  */

typedef unsigned long long u64;

// ---------------- f32x2 / async helpers ----------------
__device__ __forceinline__ void ffma2(u64& d, u64 a, u64 b) {
    asm("fma.rn.f32x2 %0, %1, %2, %0;" : "+l"(d) : "l"(a), "l"(b));
}
__device__ __forceinline__ u64 dup2(float x) {
    u64 r; unsigned xi = __float_as_uint(x);
    asm("mov.b64 %0, {%1, %1};" : "=l"(r) : "r"(xi));
    return r;
}
__device__ __forceinline__ float2 up2(u64 v) {
    float2 f;
    asm("mov.b64 {%0, %1}, %2;" : "=f"(f.x), "=f"(f.y) : "l"(v));
    return f;
}
__device__ __forceinline__ void cpa16(float* dst, const float* src) {
    unsigned d = (unsigned)__cvta_generic_to_shared(dst);
    asm volatile("cp.async.cg.shared.global [%0], [%1], 16;" :: "r"(d), "l"(src));
}
#define CP_COMMIT() asm volatile("cp.async.commit_group;")
#define CP_WAIT0()  asm volatile("cp.async.wait_group 0;")

// ---------------- device scratch (static, allocation-free) ----------------
__device__ int   d_idx[NROWS_L];
__device__ float d_WcT[256*256];                    // [c][o]
__device__ float d_WTl[4*128*128];                  // transposed w11,w12,w21,w22  [l][c][o]
__device__ float d_Wx1[128*3];
__device__ float d_Wx2[128*3];
__device__ float d_F0 [(size_t)NROWS_G*128];
__device__ float d_zgA[(size_t)NROWS_G*128];
__device__ float d_zgB[(size_t)NROWS_G*128];
__device__ float d_zlB[(size_t)NROWS_L*128];        // gemm1 output (only stored local intermediate)
__device__ float d_stats[6][2][128];
__device__ float d_ab[6][2][128];
__device__ float d_lmax[Bq*Sq*128];                 // per-group raw max (layer2 local)
__device__ float d_lmin[Bq*Sq*128];
__device__ float d_gmaxp[Bq*32*128];                // per-slice raw max (layer2 global)
__device__ float d_gminp[Bq*32*128];

// device-side buffer resolution (NEVER pass __device__ symbols from host; R5 bug)
__device__ __forceinline__ float* bufptr(int w) {
    switch (w) {
        case 1:  return d_zlB;
        case 2:  return d_zgA;
        default: return d_zgB;
    }
}

// ---------------- tiny helpers ----------------
__global__ void k_zero_stats() {
    int i = threadIdx.x;
    if (i < 128)
        for (int s = 0; s < 6; s++)
            for (int h = 0; h < 2; h++)
                d_stats[s][h][i] = 0.f;
}

__global__ void k_prep(const float* __restrict__ w10, const float* __restrict__ w20) {
    int i = blockIdx.x * blockDim.x + threadIdx.x;
    if (i < 256 * 256) {
        int c = i >> 8, o = i & 255;
        d_WcT[i] = (o < 128) ? w10[o * 259 + 3 + c] : w20[(o - 128) * 259 + 3 + c];
    }
    if (i < 128 * 3) {
        int o = i / 3, dd = i % 3;
        d_Wx1[i] = w10[o * 259 + dd];
        d_Wx2[i] = w20[o * 259 + dd];
    }
}

__global__ void k_prep2(const float* __restrict__ w11, const float* __restrict__ w12,
                        const float* __restrict__ w21, const float* __restrict__ w22) {
    int i = blockIdx.x * blockDim.x + threadIdx.x;
    int l = i >> 14, rem = i & 16383;
    int c = rem >> 7, o = rem & 127;
    const float* w = (l == 0) ? w11 : (l == 1) ? w12 : (l == 2) ? w21 : w22;
    d_WTl[i] = w[o * 128 + c];
}

// ---------------- ball query + new_xyz ----------------
__global__ void k_ballquery(const float* __restrict__ xyz,
                            const int*   __restrict__ inds,
                            float*       __restrict__ out_xyz) {
    __shared__ float sx[Np], sy[Np], sz[Np];
    int b = blockIdx.y;
    int t = threadIdx.x;
    const float* xb = xyz + (size_t)b * Np * 3;
    for (int i = t; i < Np; i += 256) {
        sx[i] = xb[i * 3 + 0];
        sy[i] = xb[i * 3 + 1];
        sz[i] = xb[i * 3 + 2];
    }
    __syncthreads();

    int w = t >> 5, lane = t & 31;
    int s = blockIdx.x * 8 + w;
    int q = inds[b * Sq + s];
    float qx = sx[q], qy = sy[q], qz = sz[q];
    if (lane == 0) out_xyz[(b * Sq + s) * 3 + 0] = qx;
    if (lane == 1) out_xyz[(b * Sq + s) * 3 + 1] = qy;
    if (lane == 2) out_xyz[(b * Sq + s) * 3 + 2] = qz;

    int* dst = d_idx + ((b * Sq + s) << 6);
    const float R2 = (float)(0.3 * 0.3);
    int count = 0, first = 0;
    for (int base = 0; base < Np; base += 32) {
        int j = base + lane;
        float dx = __fsub_rn(qx, sx[j]);
        float dy = __fsub_rn(qy, sy[j]);
        float dz = __fsub_rn(qz, sz[j]);
        float d2 = __fadd_rn(__fadd_rn(__fmul_rn(dx, dx), __fmul_rn(dy, dy)),
                             __fmul_rn(dz, dz));
        bool p = d2 < R2;
        unsigned m = __ballot_sync(0xffffffffu, p);
        if (count == 0 && m) first = base + __ffs(m) - 1;
        int pos = count + __popc(m & ((1u << lane) - 1u));
        if (p && pos < NSk) dst[pos] = j;
        count += __popc(m);
        if (count >= NSk) break;
    }
    for (int i = count + lane; i < NSk; i += 32) dst[i] = first;
}

// ---------------- dense layer0 GEMM (FFMA2 + cp.async double buffer) ----------
__global__ __launch_bounds__(256, 2) void k_l0dense(const float* __restrict__ feat,
                                                    const float* __restrict__ xyz) {
    extern __shared__ float sm[];
    float* Xc = sm;                 // 2 * 4224
    float* Ws = sm + 2 * 4224;      // 2 * 4224
    __shared__ float bsum[128], bsq[128];
    int t = threadIdx.x;
    int oB = blockIdx.y;
    int rowBase = blockIdx.x * 128;
    int b  = rowBase >> 12;
    int jb = rowBase & (Np - 1);
    if (t < 128) { bsum[t] = 0.f; bsq[t] = 0.f; }

    int ty = t >> 4, tx = t & 15;
    const float* fb = feat + (size_t)b * Cc * Np + jb;
    const float* Wg = d_WcT + oB * 128;

    auto issue = [&](int n) {
        float* xd = Xc + (n & 1) * 4224;
        float* wd = Ws + (n & 1) * 4224;
        #pragma unroll
        for (int q = 0; q < 4; q++) {
            int e = q * 256 + t;
            int c = e >> 5, seg = (e & 31) << 2;
            cpa16(xd + c * 132 + seg, fb + (size_t)(n * 32 + c) * Np + seg);
        }
        #pragma unroll
        for (int q = 0; q < 4; q++) {
            int e = q * 256 + t;
            int c = e >> 5, seg = (e & 31) << 2;
            cpa16(wd + c * 132 + seg, Wg + (n * 32 + c) * 256 + seg);
        }
        CP_COMMIT();
    };

    u64 acc[8][4] = {};
    issue(0);
    for (int i = 0; i < 8; i++) {
        CP_WAIT0();
        __syncthreads();
        if (i + 1 < 8) issue(i + 1);
        const float* Xb = Xc + (i & 1) * 4224;
        const float* Wb = Ws + (i & 1) * 4224;
        #pragma unroll 8
        for (int kk = 0; kk < 32; kk++) {
            ulonglong2 b01 = *(const ulonglong2*)(Wb + kk * 132 + tx * 8);
            ulonglong2 b23 = *(const ulonglong2*)(Wb + kk * 132 + tx * 8 + 4);
            u64 bv[4] = { b01.x, b01.y, b23.x, b23.y };
            float4 a0 = *(const float4*)(Xb + kk * 132 + ty * 8);
            float4 a1 = *(const float4*)(Xb + kk * 132 + ty * 8 + 4);
            float av[8] = { a0.x, a0.y, a0.z, a0.w, a1.x, a1.y, a1.z, a1.w };
            #pragma unroll
            for (int r = 0; r < 8; r++) {
                u64 ad = dup2(av[r]);
                #pragma unroll
                for (int c2 = 0; c2 < 4; c2++) ffma2(acc[r][c2], ad, bv[c2]);
            }
        }
        __syncthreads();
    }

    if (oB == 0) {
        #pragma unroll
        for (int r = 0; r < 8; r++) {
            float2 p0 = up2(acc[r][0]), p1 = up2(acc[r][1]);
            float2 p2 = up2(acc[r][2]), p3 = up2(acc[r][3]);
            float* dst = d_F0 + ((size_t)(rowBase + ty * 8 + r)) * 128 + tx * 8;
            *(float4*)(dst)     = make_float4(p0.x, p0.y, p1.x, p1.y);
            *(float4*)(dst + 4) = make_float4(p2.x, p2.y, p3.x, p3.y);
        }
    } else {
        float wx[8][3];
        #pragma unroll
        for (int c = 0; c < 8; c++) {
            int o = tx * 8 + c;
            wx[c][0] = d_Wx2[o * 3 + 0];
            wx[c][1] = d_Wx2[o * 3 + 1];
            wx[c][2] = d_Wx2[o * 3 + 2];
        }
        float cs[8] = {}, cq[8] = {};
        #pragma unroll
        for (int r = 0; r < 8; r++) {
            int row = rowBase + ty * 8 + r;
            const float* px = xyz + (size_t)row * 3;
            float x0 = px[0], x1 = px[1], x2 = px[2];
            float v[8];
            float2 p0 = up2(acc[r][0]), p1 = up2(acc[r][1]);
            float2 p2 = up2(acc[r][2]), p3 = up2(acc[r][3]);
            v[0]=p0.x; v[1]=p0.y; v[2]=p1.x; v[3]=p1.y;
            v[4]=p2.x; v[5]=p2.y; v[6]=p3.x; v[7]=p3.y;
            #pragma unroll
            for (int c = 0; c < 8; c++) {
                v[c] += wx[c][0]*x0 + wx[c][1]*x1 + wx[c][2]*x2;
                cs[c] += v[c]; cq[c] += v[c]*v[c];
            }
            float* dst = d_zgA + (size_t)row * 128 + tx * 8;
            *(float4*)(dst)     = make_float4(v[0], v[1], v[2], v[3]);
            *(float4*)(dst + 4) = make_float4(v[4], v[5], v[6], v[7]);
        }
        #pragma unroll
        for (int c = 0; c < 8; c++) {
            atomicAdd(&bsum[tx * 8 + c], cs[c]);
            atomicAdd(&bsq [tx * 8 + c], cq[c]);
        }
        __syncthreads();
        if (t < 128) {
            atomicAdd(&d_stats[3][0][t], bsum[t]);
            atomicAdd(&d_stats[3][1][t], bsq[t]);
        }
    }
}

// ---------------- stage-0 stats only (no z0 store; gemm1 regenerates z0) ----
__global__ void k_assemble(const float* __restrict__ xyz,
                           const float* __restrict__ nxyz) {
    __shared__ float sgx[128], sgy[128], sgz[128];
    __shared__ int   sj[128];
    int o = threadIdx.x;
    int row0 = blockIdx.x * 128;
    {
        int row = row0 + o;
        int b = row >> 15;
        int s = (row >> 6) & 511;
        int j = d_idx[row];
        const float* nx = nxyz + ((size_t)(b * Sq + s)) * 3;
        const float* px = xyz  + ((size_t)(b * Np + j)) * 3;
        sgx[o] = __fmul_rn(__fsub_rn(px[0], nx[0]), (1.0f/0.3f));
        sgy[o] = __fmul_rn(__fsub_rn(px[1], nx[1]), (1.0f/0.3f));
        sgz[o] = __fmul_rn(__fsub_rn(px[2], nx[2]), (1.0f/0.3f));
        sj[o]  = (b * Np) + j;
    }
    __syncthreads();
    float w0 = d_Wx1[o * 3 + 0], w1 = d_Wx1[o * 3 + 1], w2 = d_Wx1[o * 3 + 2];
    float s1 = 0.f, s2 = 0.f;
    #pragma unroll 4
    for (int rr = 0; rr < 128; rr++) {
        float v = d_F0[(size_t)sj[rr] * 128 + o]
                + w0 * sgx[rr] + w1 * sgy[rr] + w2 * sgz[rr];
        s1 += v; s2 += v * v;
    }
    atomicAdd(&d_stats[0][0][o], s1);
    atomicAdd(&d_stats[0][1][o], s2);
}

__global__ void k_finalize(int stage, float invCnt,
                           const float* __restrict__ g,
                           const float* __restrict__ be) {
    int o = threadIdx.x;
    float mu  = d_stats[stage][0][o] * invCnt;
    float var = d_stats[stage][1][o] * invCnt - mu * mu;
    float a = g[o] / sqrtf(var + 1e-5f);
    d_ab[stage][0][o] = a;
    d_ab[stage][1][o] = be[o] - mu * a;
}

// ---------------- unified 128x128 layer GEMM ------------------------------
// modes: 0 = local L1 (gather F0 + xyz -> store zlB + stats)
//        1 = local L2 (zlB -> group max/min + stats, no store)
//        2 = global L1 (zgA -> store zgB + stats)
//        3 = global L2 (zgB -> slice max/min + stats, no store)
// dyn smem: stX[2][4096] | Xc2[32*128 u64] | Ws[2][4224]  = 99328 B
__global__ __launch_bounds__(256, 2) void k_gemm128(int mode, int inid, int outid, int wl,
                                                    int stageIn, int stageOut,
                                                    const float* __restrict__ xyz,
                                                    const float* __restrict__ nxyz) {
    extern __shared__ float sm[];
    float* stX = sm;                       // 2 * 4096 floats
    u64*   Xc2 = (u64*)(sm + 8192);        // 32*128 u64  (A pre-duplicated, [kk][row])
    float* Ws  = sm + 8192 + 8192;         // 2 * 4224 floats
    __shared__ float sa[128], sb[128];
    __shared__ float bsum[128], bsq[128];
    __shared__ float sgx[128], sgy[128], sgz[128];
    __shared__ float sWx[3][128];
    const float* __restrict__ in = bufptr(inid);
    float* __restrict__ outb     = bufptr(outid);
    const float* WT = d_WTl + wl * 16384;
    int t = threadIdx.x;
    int rowBase = blockIdx.x * 128;
    if (t < 128) {
        sa[t] = d_ab[stageIn][0][t];
        sb[t] = d_ab[stageIn][1][t];
        bsum[t] = 0.f; bsq[t] = 0.f;
        if (mode == 0) {
            sWx[0][t] = d_Wx1[t * 3 + 0];
            sWx[1][t] = d_Wx1[t * 3 + 1];
            sWx[2][t] = d_Wx1[t * 3 + 2];
            int row = rowBase + t;
            int b = row >> 15;
            int s = (row >> 6) & 511;
            int j = d_idx[row];
            const float* nx = nxyz + ((size_t)(b * Sq + s)) * 3;
            const float* px = xyz  + ((size_t)(b * Np + j)) * 3;
            sgx[t] = __fmul_rn(__fsub_rn(px[0], nx[0]), (1.0f/0.3f));
            sgy[t] = __fmul_rn(__fsub_rn(px[1], nx[1]), (1.0f/0.3f));
            sgz[t] = __fmul_rn(__fsub_rn(px[2], nx[2]), (1.0f/0.3f));
        }
    }
    int ty = t >> 4, tx = t & 15;

    // per-thread source row bases for the X gather (4 rows/thread, 16B segment each)
    const float* rb[4];
    {
        int seg = (t & 7) << 2;
        #pragma unroll
        for (int q = 0; q < 4; q++) {
            int r = q * 32 + (t >> 3);
            if (mode == 0) {
                int row = rowBase + r;
                int b = row >> 15;
                int j = d_idx[row];
                rb[q] = d_F0 + ((size_t)(b * Np + j)) * 128 + seg;
            } else {
                rb[q] = in + ((size_t)(rowBase + r)) * 128 + seg;
            }
        }
    }

    auto issue = [&](int n) {
        float* xd = stX + (n & 1) * 4096;
        float* wd = Ws  + (n & 1) * 4224;
        int seg = (t & 7) << 2;
        #pragma unroll
        for (int q = 0; q < 4; q++) {
            int r = q * 32 + (t >> 3);
            cpa16(xd + r * 32 + seg, rb[q] + n * 32);
        }
        #pragma unroll
        for (int q = 0; q < 4; q++) {
            int e = q * 256 + t;
            int c = e >> 5, sg = (e & 31) << 2;
            cpa16(wd + c * 132 + sg, WT + (n * 32 + c) * 128 + sg);
        }
        CP_COMMIT();
    };

    u64 acc[8][4] = {};
    issue(0);
    int tr_r = t >> 1, tr_c0 = (t & 1) << 4;
    for (int i = 0; i < 4; i++) {
        CP_WAIT0();
        __syncthreads();
        if (i + 1 < 4) issue(i + 1);
        // transform: (+xyz term if mode0) -> BN+ReLU -> duplicated pair store [kk][row]
        {
            const float* src = stX + (i & 1) * 4096 + tr_r * 32 + tr_c0;
            float gx = 0.f, gy = 0.f, gz = 0.f;
            if (mode == 0) { gx = sgx[tr_r]; gy = sgy[tr_r]; gz = sgz[tr_r]; }
            int k0 = i * 32 + tr_c0;
            #pragma unroll
            for (int j = 0; j < 16; j++) {
                float f = src[j];
                int kc = k0 + j;
                if (mode == 0)
                    f += sWx[0][kc] * gx + sWx[1][kc] * gy + sWx[2][kc] * gz;
                float y = fmaxf(fmaf(sa[kc], f, sb[kc]), 0.f);
                Xc2[(tr_c0 + j) * 128 + tr_r] = dup2(y);
            }
        }
        __syncthreads();
        const float* Wb = Ws + (i & 1) * 4224;
        #pragma unroll 8
        for (int kk = 0; kk < 32; kk++) {
            ulonglong2 b01 = *(const ulonglong2*)(Wb + kk * 132 + tx * 8);
            ulonglong2 b23 = *(const ulonglong2*)(Wb + kk * 132 + tx * 8 + 4);
            u64 bv[4] = { b01.x, b01.y, b23.x, b23.y };
            ulonglong2 a01 = *(const ulonglong2*)(Xc2 + kk * 128 + ty * 8);
            ulonglong2 a23 = *(const ulonglong2*)(Xc2 + kk * 128 + ty * 8 + 2);
            ulonglong2 a45 = *(const ulonglong2*)(Xc2 + kk * 128 + ty * 8 + 4);
            ulonglong2 a67 = *(const ulonglong2*)(Xc2 + kk * 128 + ty * 8 + 6);
            u64 av[8] = { a01.x, a01.y, a23.x, a23.y, a45.x, a45.y, a67.x, a67.y };
            #pragma unroll
            for (int r = 0; r < 8; r++)
                #pragma unroll
                for (int c2 = 0; c2 < 4; c2++) ffma2(acc[r][c2], av[r], bv[c2]);
        }
        __syncthreads();   // Xc2 reused next iter
    }

    // ---------------- epilogue ----------------
    float cs[8] = {}, cq[8] = {};
    float mx[8], mn[8];
    #pragma unroll
    for (int c = 0; c < 8; c++) { mx[c] = -3.4e38f; mn[c] = 3.4e38f; }
    bool storeZ = (mode == 0) || (mode == 2);
    #pragma unroll
    for (int r = 0; r < 8; r++) {
        float v[8];
        float2 p0 = up2(acc[r][0]), p1 = up2(acc[r][1]);
        float2 p2 = up2(acc[r][2]), p3 = up2(acc[r][3]);
        v[0]=p0.x; v[1]=p0.y; v[2]=p1.x; v[3]=p1.y;
        v[4]=p2.x; v[5]=p2.y; v[6]=p3.x; v[7]=p3.y;
        #pragma unroll
        for (int c = 0; c < 8; c++) {
            cs[c] += v[c]; cq[c] += v[c]*v[c];
            mx[c] = fmaxf(mx[c], v[c]); mn[c] = fminf(mn[c], v[c]);
        }
        if (storeZ) {
            float* dst = outb + ((size_t)(rowBase + ty * 8 + r)) * 128 + tx * 8;
            *(float4*)(dst)     = make_float4(v[0], v[1], v[2], v[3]);
            *(float4*)(dst + 4) = make_float4(v[4], v[5], v[6], v[7]);
        }
    }
    #pragma unroll
    for (int c = 0; c < 8; c++) {
        atomicAdd(&bsum[tx * 8 + c], cs[c]);
        atomicAdd(&bsq [tx * 8 + c], cq[c]);
    }

    if (!storeZ) {
        // reduce per-column max/min across ty into stX scratch (free now)
        float* redmx = stX;            // [16][128]
        float* redmn = stX + 2048;     // [16][128]
        #pragma unroll
        for (int c = 0; c < 8; c++) {
            redmx[ty * 128 + tx * 8 + c] = mx[c];
            redmn[ty * 128 + tx * 8 + c] = mn[c];
        }
        __syncthreads();
        if (mode == 1) {
            // two groups of 64 rows per block
            int g = t >> 7, o = t & 127;
            float m = -3.4e38f, n2 = 3.4e38f;
            #pragma unroll
            for (int k = 0; k < 8; k++) {
                m  = fmaxf(m,  redmx[(g * 8 + k) * 128 + o]);
                n2 = fminf(n2, redmn[(g * 8 + k) * 128 + o]);
            }
            int grp = blockIdx.x * 2 + g;
            d_lmax[grp * 128 + o] = m;
            d_lmin[grp * 128 + o] = n2;
        } else if (t < 128) {
            float m = -3.4e38f, n2 = 3.4e38f;
            #pragma unroll
            for (int k = 0; k < 16; k++) {
                m  = fmaxf(m,  redmx[k * 128 + t]);
                n2 = fminf(n2, redmn[k * 128 + t]);
            }
            d_gmaxp[blockIdx.x * 128 + t] = m;
            d_gminp[blockIdx.x * 128 + t] = n2;
        }
    }
    __syncthreads();
    if (t < 128) {
        atomicAdd(&d_stats[stageOut][0][t], bsum[t]);
        atomicAdd(&d_stats[stageOut][1][t], bsq[t]);
    }
}

// ---------------- finishers ----------------
__global__ void k_lfinish(float* __restrict__ outF) {
    int bs = blockIdx.x;            // b*512+s
    int o  = threadIdx.x;
    float a = d_ab[2][0][o], bb = d_ab[2][1][o];
    float M = (a >= 0.f) ? d_lmax[bs * 128 + o] : d_lmin[bs * 128 + o];
    float val = fmaxf(fmaf(a, M, bb), 0.f);
    int b = bs >> 9, s = bs & 511;
    outF[((size_t)b * 256 + o) * 512 + s] = val;
}

__global__ void k_gfinish(float* __restrict__ outF) {
    __shared__ float smx[128];
    int b = blockIdx.x, t = threadIdx.x;
    if (t < 128) {
        float a = d_ab[5][0][t], bb = d_ab[5][1][t];
        float m = -3.4e38f, n2 = 3.4e38f;
        for (int sl = 0; sl < 32; sl++) {
            m  = fmaxf(m,  d_gmaxp[(b * 32 + sl) * 128 + t]);
            n2 = fminf(n2, d_gminp[(b * 32 + sl) * 128 + t]);
        }
        float M = (a >= 0.f) ? m : n2;
        smx[t] = fmaxf(fmaf(a, M, bb), 0.f);
    }
    __syncthreads();
    for (int i = t; i < 128 * 512; i += 256) {
        int o = i >> 9, s = i & 511;
        outF[((size_t)b * 256 + 128 + o) * 512 + s] = smx[o];
    }
}

// ---------------- launch ----------------
extern "C" void kernel_launch(void* const* d_in, const int* in_sizes, int n_in,
                              void* d_out, int out_size) {
    (void)in_sizes; (void)n_in; (void)out_size;
    const float* xyz  = (const float*)d_in[0];
    const float* feat = (const float*)d_in[1];
    const int*   inds = (const int*)  d_in[2];
    const float* w10  = (const float*)d_in[3];
    const float* g10  = (const float*)d_in[4];
    const float* be10 = (const float*)d_in[5];
    const float* w11  = (const float*)d_in[6];
    const float* g11  = (const float*)d_in[7];
    const float* be11 = (const float*)d_in[8];
    const float* w12  = (const float*)d_in[9];
    const float* g12  = (const float*)d_in[10];
    const float* be12 = (const float*)d_in[11];
    const float* w20  = (const float*)d_in[12];
    const float* g20  = (const float*)d_in[13];
    const float* be20 = (const float*)d_in[14];
    const float* w21  = (const float*)d_in[15];
    const float* g21  = (const float*)d_in[16];
    const float* be21 = (const float*)d_in[17];
    const float* w22  = (const float*)d_in[18];
    const float* g22  = (const float*)d_in[19];
    const float* be22 = (const float*)d_in[20];

    float* out      = (float*)d_out;
    float* out_xyz  = out;                       // (B,S,3)
    float* out_feat = out + (size_t)Bq * Sq * 3; // (B,256,S)

    const float invL = 1.0f / (float)NROWS_L;
    const float invG = 1.0f / (float)NROWS_G;

    const int SMEM_L0 = 2 * 4224 * 2 * 4;                      // 67584
    const int SMEM_GM = (8192 + 8192 + 2 * 4224) * 4;          // 99328
    static int attr_done = 0;
    if (!attr_done) {
        cudaFuncSetAttribute(k_l0dense, cudaFuncAttributeMaxDynamicSharedMemorySize, SMEM_L0);
        cudaFuncSetAttribute(k_gemm128, cudaFuncAttributeMaxDynamicSharedMemorySize, SMEM_GM);
        attr_done = 1;
    }

    k_zero_stats<<<1, 128>>>();
    k_prep<<<256, 256>>>(w10, w20);
    k_prep2<<<256, 256>>>(w11, w12, w21, w22);
    k_ballquery<<<dim3(Sq / 8, Bq), 256>>>(xyz, inds, out_xyz);

    // layer 0: dense feature GEMM (F0 + global z0 with fused stage3 stats)
    k_l0dense<<<dim3(256, 2), 256, SMEM_L0>>>(feat, xyz);
    k_finalize<<<1, 128>>>(3, invG, g20, be20);

    // local stage0 stats (no store)
    k_assemble<<<2048, 128>>>(xyz, out_xyz);
    k_finalize<<<1, 128>>>(0, invL, g10, be10);

    // local L1: gather F0 -> zlB (+stats1);  L2: zlB -> group max/min (+stats2)
    k_gemm128<<<NROWS_L / 128, 256, SMEM_GM>>>(0, 1, 1, 0, 0, 1, xyz, out_xyz);
    k_finalize<<<1, 128>>>(1, invL, g11, be11);
    k_gemm128<<<NROWS_L / 128, 256, SMEM_GM>>>(1, 1, 1, 1, 1, 2, xyz, out_xyz);
    k_finalize<<<1, 128>>>(2, invL, g12, be12);
    k_lfinish<<<Bq * Sq, 128>>>(out_feat);

    // global L1: zgA -> zgB (+stats4);  L2: zgB -> slice max/min (+stats5)
    k_gemm128<<<NROWS_G / 128, 256, SMEM_GM>>>(2, 2, 3, 2, 3, 4, xyz, out_xyz);
    k_finalize<<<1, 128>>>(4, invG, g21, be21);
    k_gemm128<<<NROWS_G / 128, 256, SMEM_GM>>>(3, 3, 3, 3, 4, 5, xyz, out_xyz);
    k_finalize<<<1, 128>>>(5, invG, g22, be22);
    k_gfinish<<<Bq, 256>>>(out_feat);
}